// round 9
// baseline (speedup 1.0000x reference)
#include <cuda_runtime.h>
#include <cuda_fp16.h>
#include <cstdint>

// ============================================================================
// NCMOpenMax: probas = softmax(cos(X, muK), axis=1)
//   X [262144,128] f32, muK [512,128] f32, out [262144,512] f32
//
// Three kernels:
//  1) ncm_prep : normalize muK -> permuted fp16 mma fragments (g_bfrag)
//  2) ncm_xprep: X -> fp16 (g_xh) + per-row log2e/||x|| (g_nrm)   [one shot]
//  3) ncm_main : persistent 8-warp CTAs, B entirely in registers,
//     tile = 32 rows x 512 classes. Per tile (R5 ordering, proven fastest):
//       cp.async(next A, fire&forget) -> prefetch norms -> mma ->
//       exp+rs -> bar -> pass2 (LDS.128 dens + STG.128 stores) -> wait -> bar
//     cos<=1 => fixed shift exp2(acc*c1 - log2e): exact softmax, no max pass.
// ============================================================================

static constexpr int DDIM = 128;
static constexpr int KCLS = 512;
static constexpr int BM   = 32;
static constexpr int NMAX = 262144;

// B fragments fp16: [s(8)][t(64)][lane(32)] x uint2 (4 halves)
__device__ __half g_bfrag[8 * 64 * 32 * 4];     // 128 KB
__device__ __half g_xh[(size_t)NMAX * DDIM];    // 64 MB, X in fp16
__device__ float  g_nrm[NMAX];                  // log2e / ||x_row||

// ---- smem layout (bytes) ----
static constexpr int A_STRIDE = 272;              // 256 B row + 16 B pad
static constexpr int A_BYTES  = BM * A_STRIDE;    // 8704
static constexpr int SM_A0    = 0;
static constexpr int SM_A1    = A_BYTES;          // 8704
static constexpr int SM_RS    = 2 * A_BYTES;      // 17408 (32 x 8 f32)
static constexpr int SM_TOTAL = SM_RS + 1024;     // 18432

__device__ __forceinline__ uint32_t smem_u32(const void* p) {
    uint32_t a;
    asm("{ .reg .u64 t; cvta.to.shared.u64 t, %1; cvt.u32.u64 %0, t; }"
        : "=r"(a) : "l"(p));
    return a;
}

#define CP_ASYNC16(dst_u32, src_ptr) \
    asm volatile("cp.async.cg.shared.global [%0], [%1], 16;" \
                 :: "r"(dst_u32), "l"(src_ptr) : "memory")

__device__ __forceinline__ void mma_f16(float* d, const uint32_t* a,
                                        uint32_t b0, uint32_t b1) {
    asm volatile(
        "mma.sync.aligned.m16n8k16.row.col.f32.f16.f16.f32 "
        "{%0,%1,%2,%3},{%4,%5,%6,%7},{%8,%9},{%0,%1,%2,%3};"
        : "+f"(d[0]), "+f"(d[1]), "+f"(d[2]), "+f"(d[3])
        : "r"(a[0]), "r"(a[1]), "r"(a[2]), "r"(a[3]), "r"(b0), "r"(b1));
}

__device__ __forceinline__ float ex2f(float x) {
    float r;
    asm("ex2.approx.ftz.f32 %0, %1;" : "=f"(r) : "f"(x));
    return r;
}

constexpr float LOG2E = 1.4426950408889634f;

// ---------------- prep 1: normalize muK -> permuted fp16 fragments ---------

__global__ void ncm_prep(const float* __restrict__ muK) {
    __shared__ float pp[4];
    int n = blockIdx.x;       // class (output column)
    int k = threadIdx.x;      // feature
    float v = muK[n * DDIM + k];
    float ss = v * v;
    #pragma unroll
    for (int o = 16; o > 0; o >>= 1)
        ss += __shfl_xor_sync(0xffffffffu, ss, o);
    if ((k & 31) == 0) pp[k >> 5] = ss;
    __syncthreads();
    float inv = 1.0f / fmaxf(sqrtf(pp[0] + pp[1] + pp[2] + pp[3]), 1e-8f);

    // column permutation (validated R5): output col n -> fragment F so a
    // thread's 4 values per tile-pair are contiguous output columns.
    int wb = n >> 6, nl = n & 63;
    int u  = nl >> 4, j = nl & 15;
    int kq = j >> 2, hi = (j >> 1) & 1, e = j & 1;
    int F  = wb * 64 + u * 16 + hi * 8 + kq * 2 + e;
    int t  = F >> 3;
    int fc = F & 7;

    int s    = k >> 4;
    int kk   = k & 15;
    int lane = fc * 4 + ((kk & 7) >> 1);
    int idx  = ((kk >= 8) ? 2 : 0) + (kk & 1);
    g_bfrag[(((s * 64 + t) * 32 + lane) << 2) + idx] = __float2half_rn(v * inv);
}

// ---------------- prep 2: X -> fp16 + row norms -----------------------------

__global__ void __launch_bounds__(256, 4)
ncm_xprep(const float* __restrict__ X, int N) {
    int idx = blockIdx.x * 256 + threadIdx.x;
    int r = idx >> 3;          // row
    int q = idx & 7;           // 16-float segment of that row
    if (r >= N) return;

    const float4* src = reinterpret_cast<const float4*>(X) + (size_t)r * 32 + q * 4;
    float4 v[4];
    #pragma unroll
    for (int i = 0; i < 4; i++) v[i] = src[i];

    float ss = 0.f;
    #pragma unroll
    for (int i = 0; i < 4; i++)
        ss += v[i].x * v[i].x + v[i].y * v[i].y +
              v[i].z * v[i].z + v[i].w * v[i].w;
    ss += __shfl_xor_sync(0xffffffffu, ss, 1);
    ss += __shfl_xor_sync(0xffffffffu, ss, 2);
    ss += __shfl_xor_sync(0xffffffffu, ss, 4);
    if (q == 0) g_nrm[r] = LOG2E / fmaxf(sqrtf(ss), 1e-8f);

    uint32_t h[8];
    #pragma unroll
    for (int i = 0; i < 4; i++) {
        __half2 h0 = __floats2half2_rn(v[i].x, v[i].y);
        __half2 h1 = __floats2half2_rn(v[i].z, v[i].w);
        h[2 * i + 0] = *reinterpret_cast<uint32_t*>(&h0);
        h[2 * i + 1] = *reinterpret_cast<uint32_t*>(&h1);
    }
    uint4* dst = reinterpret_cast<uint4*>(
        reinterpret_cast<char*>(g_xh) + (size_t)r * 256 + q * 32);
    dst[0] = make_uint4(h[0], h[1], h[2], h[3]);
    dst[1] = make_uint4(h[4], h[5], h[6], h[7]);
}

// ---------------- main: persistent GEMM + fused softmax ----------------

__global__ void __launch_bounds__(256, 1)
ncm_main(float* __restrict__ out, int tiles, int nct) {
    extern __shared__ char smem[];
    const uint32_t sb = smem_u32(smem);
    const int tid  = threadIdx.x;
    const int lane = tid & 31;
    const int wid  = tid >> 5;
    const int g    = lane >> 2;
    const int kq   = lane & 3;

    // ldmatrix lane addressing (x4: two 8-row mats x two 8-col k-halves)
    const int m_    = lane >> 3;
    const int lrow  = ((m_ & 1) << 3) + (lane & 7);
    const int lkoff = (m_ >> 1) << 4;

    float* rs_arr = reinterpret_cast<float*>(smem + SM_RS);  // [row][warp8]

    // ---- B into registers: warp wid owns classes [wid*64, wid*64+64) ----
    uint2 breg[8][8];
    {
        const uint2* bsrc = reinterpret_cast<const uint2*>(g_bfrag);
        #pragma unroll
        for (int s = 0; s < 8; s++)
            #pragma unroll
            for (int t = 0; t < 8; t++)
                breg[s][t] = bsrc[(s * 64 + wid * 8 + t) * 32 + lane];
    }

    const int r = tid >> 3;   // A row on copy path (32 rows, 8 thr/row)
    const int q = tid & 7;    // 32-byte segment within row

    // cp.async copy of one 32x128 fp16 A tile into buf (8 KB)
    auto copyA = [&](int t_, int buf) {
        const char* src = reinterpret_cast<const char*>(g_xh)
                          + ((size_t)t_ * BM + r) * 256 + q * 32;
        uint32_t dst = sb + (buf ? SM_A1 : SM_A0) + r * A_STRIDE + q * 32;
        CP_ASYNC16(dst, src);
        CP_ASYNC16(dst + 16, src + 16);
    };

    // ---- preamble: tile0 into buf0 ----
    copyA(blockIdx.x, 0);
    asm volatile("cp.async.commit_group;" ::: "memory");
    asm volatile("cp.async.wait_group 0;" ::: "memory");
    __syncthreads();

    int p = 0;
    for (int tile = blockIdx.x; tile < tiles; tile += nct) {
        const bool hn = (tile + nct) < tiles;

        // ---- issue next-tile cp.async (fire & forget, no registers) ----
        if (hn) {
            copyA(tile + nct, p ^ 1);
            asm volatile("cp.async.commit_group;" ::: "memory");
        }

        // ---- prefetch this tile's norms (4 rows per thread) ----
        float cn[4];
        #pragma unroll
        for (int i = 0; i < 4; i++)
            cn[i] = __ldg(&g_nrm[(size_t)tile * BM + i * 8 + g]);

        // ---- mma phase: 32 rows x 512 cols, B from regs ----
        float acc[2][8][4];
        #pragma unroll
        for (int sl = 0; sl < 2; sl++)
            #pragma unroll
            for (int t = 0; t < 8; t++)
                #pragma unroll
                for (int c = 0; c < 4; c++) acc[sl][t][c] = 0.f;

        const uint32_t abase = sb + (p ? SM_A1 : SM_A0);
        #pragma unroll
        for (int s = 0; s < 8; s++) {
            uint32_t a0[4], a1[4];
            uint32_t ad0 = abase + (uint32_t)(lrow * A_STRIDE + s * 32 + lkoff);
            asm volatile(
                "ldmatrix.sync.aligned.m8n8.x4.shared.b16 {%0,%1,%2,%3},[%4];"
                : "=r"(a0[0]), "=r"(a0[1]), "=r"(a0[2]), "=r"(a0[3])
                : "r"(ad0));
            asm volatile(
                "ldmatrix.sync.aligned.m8n8.x4.shared.b16 {%0,%1,%2,%3},[%4];"
                : "=r"(a1[0]), "=r"(a1[1]), "=r"(a1[2]), "=r"(a1[3])
                : "r"(ad0 + 16 * A_STRIDE));
            #pragma unroll
            for (int t = 0; t < 8; t++) {
                mma_f16(acc[0][t], a0, breg[s][t].x, breg[s][t].y);
                mma_f16(acc[1][t], a1, breg[s][t].x, breg[s][t].y);
            }
        }

        // ---- pass 1: e = exp2(acc*c1 - log2e), partial row sums -> rs ----
        #pragma unroll
        for (int sl = 0; sl < 2; sl++) {
            #pragma unroll
            for (int h = 0; h < 2; h++) {
                const int row = sl * 16 + h * 8 + g;
                const float c1 = cn[sl * 2 + h];
                float psum = 0.f;
                #pragma unroll
                for (int t = 0; t < 8; t++) {
                    float e0 = ex2f(fmaf(acc[sl][t][h * 2 + 0], c1, -LOG2E));
                    float e1 = ex2f(fmaf(acc[sl][t][h * 2 + 1], c1, -LOG2E));
                    acc[sl][t][h * 2 + 0] = e0;
                    acc[sl][t][h * 2 + 1] = e1;
                    psum += e0 + e1;
                }
                psum += __shfl_xor_sync(0xffffffffu, psum, 1);
                psum += __shfl_xor_sync(0xffffffffu, psum, 2);
                if (kq == 0) rs_arr[row * 8 + wid] = psum;
            }
        }
        __syncthreads();   // rs visible; stores can stream per-warp now

        // ---- pass 2: denominators (2x LDS.128), scale, STG.128 ----
        const float4* rsq = reinterpret_cast<const float4*>(rs_arr);
        #pragma unroll
        for (int sl = 0; sl < 2; sl++) {
            #pragma unroll
            for (int h = 0; h < 2; h++) {
                const int row = sl * 16 + h * 8 + g;
                float4 d0 = rsq[row * 2];
                float4 d1 = rsq[row * 2 + 1];
                const float iv = 1.0f / (d0.x + d0.y + d0.z + d0.w +
                                         d1.x + d1.y + d1.z + d1.w);
                float* op = out + ((size_t)tile * BM + row) * KCLS
                                + wid * 64 + kq * 4;
                #pragma unroll
                for (int u = 0; u < 4; u++) {
                    float4 v;
                    v.x = acc[sl][2 * u + 0][h * 2 + 0] * iv;
                    v.y = acc[sl][2 * u + 0][h * 2 + 1] * iv;
                    v.z = acc[sl][2 * u + 1][h * 2 + 0] * iv;
                    v.w = acc[sl][2 * u + 1][h * 2 + 1] * iv;
                    *reinterpret_cast<float4*>(op + u * 16) = v;
                }
            }
        }

        // ---- next A landed? then release buffers for next iteration ----
        if (hn) asm volatile("cp.async.wait_group 0;" ::: "memory");
        __syncthreads();
        p ^= 1;
    }
}

// ---------------- launch ----------------

extern "C" void kernel_launch(void* const* d_in, const int* in_sizes, int n_in,
                              void* d_out, int out_size) {
    const float* X   = (const float*)d_in[0];   // [N,128]
    const float* muK = (const float*)d_in[1];   // [512,128]
    float* out = (float*)d_out;                 // [N,512]

    static int sms = 0;
    if (!sms) {
        cudaDeviceGetAttribute(&sms, cudaDevAttrMultiProcessorCount, 0);
        if (sms <= 0) sms = 148;
        cudaFuncSetAttribute(ncm_main,
                             cudaFuncAttributeMaxDynamicSharedMemorySize,
                             SM_TOTAL);
    }

    int N = in_sizes[0] / DDIM;          // 262144
    int tiles = N / BM;                  // 8192
    int nct = sms < tiles ? sms : tiles;

    ncm_prep<<<KCLS, DDIM>>>(muK);
    ncm_xprep<<<(N * 8 + 255) / 256, 256>>>(X, N);
    ncm_main<<<nct, 256, SM_TOTAL>>>(out, tiles, nct);
}

// round 10
// speedup vs baseline: 1.2356x; 1.2356x over previous
#include <cuda_runtime.h>
#include <cuda_fp16.h>
#include <cstdint>

// ============================================================================
// NCMOpenMax: probas = softmax(cos(X, muK), axis=1)
//   X [262144,128] f32, muK [512,128] f32, out [262144,512] f32
//
// fp16 mma.sync.m16n8k16, persistent CTAs (1/SM, 256 thr = 8 warps).
// B (normalized muK, fp16 fragments) entirely in registers: warp owns 64
// classes -> 128 B-regs/thread (B exactly fills half the RF once).
// Tile = 32 rows x 512 classes. A double-buffered in smem.
// R5 ordering (proven fastest): mma -> LDG(next) -> exp+rs -> bar ->
//   pass2 (LDS.128 dens + st.global.cs stores) -> stage(next A) -> bar.
// rs layout [row][warp] so denominators are 2x LDS.128 (R7's isolated win).
// Prep kernel permutes class columns so pass 2 is pure 16B stores.
// cos<=1 => fixed shift exp2(s*c1 - log2e): exact softmax, no max pass.
// ============================================================================

static constexpr int DDIM = 128;
static constexpr int KCLS = 512;
static constexpr int BM   = 32;

// B fragments fp16: [s(8)][t(64)][lane(32)] x uint2 (4 halves)
__device__ __half g_bfrag[8 * 64 * 32 * 4];   // 128 KB

// ---- smem layout (bytes) ----
static constexpr int A_STRIDE = 272;              // 128 halves + 16B pad
static constexpr int A_BYTES  = BM * A_STRIDE;    // 8704
static constexpr int SM_A0    = 0;
static constexpr int SM_A1    = A_BYTES;          // 8704
static constexpr int SM_NRM   = 2 * A_BYTES;      // 17408 (2 x 32 f32)
static constexpr int SM_RS    = SM_NRM + 256;     // 17664 (32 x 8 f32)
static constexpr int SM_TOTAL = SM_RS + 1024;     // 18688

__device__ __forceinline__ uint32_t smem_u32(const void* p) {
    uint32_t a;
    asm("{ .reg .u64 t; cvta.to.shared.u64 t, %1; cvt.u32.u64 %0, t; }"
        : "=r"(a) : "l"(p));
    return a;
}

__device__ __forceinline__ void mma_f16(float* d, const uint32_t* a,
                                        uint32_t b0, uint32_t b1) {
    asm volatile(
        "mma.sync.aligned.m16n8k16.row.col.f32.f16.f16.f32 "
        "{%0,%1,%2,%3},{%4,%5,%6,%7},{%8,%9},{%0,%1,%2,%3};"
        : "+f"(d[0]), "+f"(d[1]), "+f"(d[2]), "+f"(d[3])
        : "r"(a[0]), "r"(a[1]), "r"(a[2]), "r"(a[3]), "r"(b0), "r"(b1));
}

__device__ __forceinline__ float ex2f(float x) {
    float r;
    asm("ex2.approx.ftz.f32 %0, %1;" : "=f"(r) : "f"(x));
    return r;
}

// streaming (evict-first) 16B store
__device__ __forceinline__ void stg_cs(float* p, float4 v) {
    asm volatile("st.global.cs.v4.f32 [%0], {%1,%2,%3,%4};"
                 :: "l"(p), "f"(v.x), "f"(v.y), "f"(v.z), "f"(v.w)
                 : "memory");
}

// ---------------- prep: normalize muK -> permuted fp16 fragments -----------

__global__ void ncm_prep(const float* __restrict__ muK) {
    __shared__ float pp[4];
    int n = blockIdx.x;       // class (output column)
    int k = threadIdx.x;      // feature
    float v = muK[n * DDIM + k];
    float ss = v * v;
    #pragma unroll
    for (int o = 16; o > 0; o >>= 1)
        ss += __shfl_xor_sync(0xffffffffu, ss, o);
    if ((k & 31) == 0) pp[k >> 5] = ss;
    __syncthreads();
    float inv = 1.0f / fmaxf(sqrtf(pp[0] + pp[1] + pp[2] + pp[3]), 1e-8f);

    // column permutation (validated R5): output col n -> fragment F so a
    // thread's 4 values per tile-pair are contiguous output columns.
    // n = wb*64 + u*16 + kq*4 + hi*2 + e -> F = wb*64 + u*16 + hi*8 + kq*2 + e
    int wb = n >> 6, nl = n & 63;
    int u  = nl >> 4, j = nl & 15;
    int kq = j >> 2, hi = (j >> 1) & 1, e = j & 1;
    int F  = wb * 64 + u * 16 + hi * 8 + kq * 2 + e;
    int t  = F >> 3;                 // 8-class fragment tile
    int fc = F & 7;                  // column within tile

    // m16n8k16 .col B fragment addressing
    int s    = k >> 4;
    int kk   = k & 15;
    int lane = fc * 4 + ((kk & 7) >> 1);
    int idx  = ((kk >= 8) ? 2 : 0) + (kk & 1);
    g_bfrag[(((s * 64 + t) * 32 + lane) << 2) + idx] = __float2half_rn(v * inv);
}

// ---------------- main: persistent GEMM + fused softmax ----------------

__global__ void __launch_bounds__(256, 1)
ncm_main(const float* __restrict__ X, float* __restrict__ out,
         int tiles, int nct) {
    extern __shared__ char smem[];
    const uint32_t sb = smem_u32(smem);
    const int tid  = threadIdx.x;
    const int lane = tid & 31;
    const int wid  = tid >> 5;
    const int g    = lane >> 2;
    const int kq   = lane & 3;

    // ldmatrix lane addressing (x4: two 8-row mats x two 8-col k-halves)
    const int m_    = lane >> 3;
    const int lrow  = ((m_ & 1) << 3) + (lane & 7);
    const int lkoff = (m_ >> 1) << 4;

    float* nrm_arr = reinterpret_cast<float*>(smem + SM_NRM);
    float* rs_arr  = reinterpret_cast<float*>(smem + SM_RS); // [row][warp8]

    // ---- B into registers: warp wid owns classes [wid*64, wid*64+64) ----
    uint2 breg[8][8];
    {
        const uint2* bsrc = reinterpret_cast<const uint2*>(g_bfrag);
        #pragma unroll
        for (int s = 0; s < 8; s++)
            #pragma unroll
            for (int t = 0; t < 8; t++)
                breg[s][t] = bsrc[(s * 64 + wid * 8 + t) * 32 + lane];
    }

    const int r = tid >> 3;   // A row owned on load path (32 rows, 8 thr/row)
    const int q = tid & 7;    // float4 phase within row
    constexpr float LOG2E = 1.4426950408889634f;

    // stage: given x[4] (float4 f32), write inv-norm*log2e and f16 A tile
    auto stage = [&](const float4* x, int buf) {
        float ss = 0.f;
        #pragma unroll
        for (int i = 0; i < 4; i++)
            ss += x[i].x * x[i].x + x[i].y * x[i].y +
                  x[i].z * x[i].z + x[i].w * x[i].w;
        ss += __shfl_xor_sync(0xffffffffu, ss, 1);
        ss += __shfl_xor_sync(0xffffffffu, ss, 2);
        ss += __shfl_xor_sync(0xffffffffu, ss, 4);
        if (q == 0)
            nrm_arr[buf * 32 + r] = LOG2E / fmaxf(sqrtf(ss), 1e-8f);
        char* adst = smem + (buf ? SM_A1 : SM_A0) + r * A_STRIDE;
        #pragma unroll
        for (int i = 0; i < 4; i++) {
            __half2 h0 = __floats2half2_rn(x[i].x, x[i].y);
            __half2 h1 = __floats2half2_rn(x[i].z, x[i].w);
            uint2 u2;
            u2.x = *reinterpret_cast<uint32_t*>(&h0);
            u2.y = *reinterpret_cast<uint32_t*>(&h1);
            *reinterpret_cast<uint2*>(adst + (q + 8 * i) * 8) = u2;
        }
    };

    // ---- preamble: stage tile0 ----
    {
        const float4* src = reinterpret_cast<const float4*>(X)
                            + ((size_t)blockIdx.x * BM + r) * 32;
        float4 x[4];
        #pragma unroll
        for (int i = 0; i < 4; i++) x[i] = src[q + 8 * i];
        stage(x, 0);
    }
    __syncthreads();

    int p = 0;
    for (int tile = blockIdx.x; tile < tiles; tile += nct) {
        const bool hn = (tile + nct) < tiles;

        // ---- mma phase: 32 rows x 512 cols, B from regs ----
        float acc[2][8][4];
        #pragma unroll
        for (int sl = 0; sl < 2; sl++)
            #pragma unroll
            for (int t = 0; t < 8; t++)
                #pragma unroll
                for (int c = 0; c < 4; c++) acc[sl][t][c] = 0.f;

        const uint32_t abase = sb + (p ? SM_A1 : SM_A0);
        #pragma unroll
        for (int s = 0; s < 8; s++) {
            uint32_t a0[4], a1[4];
            uint32_t ad0 = abase + (uint32_t)(lrow * A_STRIDE + s * 32 + lkoff);
            asm volatile(
                "ldmatrix.sync.aligned.m8n8.x4.shared.b16 {%0,%1,%2,%3},[%4];"
                : "=r"(a0[0]), "=r"(a0[1]), "=r"(a0[2]), "=r"(a0[3])
                : "r"(ad0));
            asm volatile(
                "ldmatrix.sync.aligned.m8n8.x4.shared.b16 {%0,%1,%2,%3},[%4];"
                : "=r"(a1[0]), "=r"(a1[1]), "=r"(a1[2]), "=r"(a1[3])
                : "r"(ad0 + 16 * A_STRIDE));
            #pragma unroll
            for (int t = 0; t < 8; t++) {
                mma_f16(acc[0][t], a0, breg[s][t].x, breg[s][t].y);
                mma_f16(acc[1][t], a1, breg[s][t].x, breg[s][t].y);
            }
        }

        // ---- issue next-tile A loads (latency hidden under exp + pass2) ----
        float4 x[4];
        if (hn) {
            const float4* src = reinterpret_cast<const float4*>(X)
                                + ((size_t)(tile + nct) * BM + r) * 32;
            #pragma unroll
            for (int i = 0; i < 4; i++) x[i] = src[q + 8 * i];
        }

        // ---- pass 1: e = exp2(acc*c1 - log2e), partial row sums -> rs ----
        const float* nrmc = nrm_arr + p * 32;
        #pragma unroll
        for (int sl = 0; sl < 2; sl++) {
            #pragma unroll
            for (int h = 0; h < 2; h++) {
                const int row = sl * 16 + h * 8 + g;
                const float c1 = nrmc[row];
                float psum = 0.f;
                #pragma unroll
                for (int t = 0; t < 8; t++) {
                    float e0 = ex2f(fmaf(acc[sl][t][h * 2 + 0], c1, -LOG2E));
                    float e1 = ex2f(fmaf(acc[sl][t][h * 2 + 1], c1, -LOG2E));
                    acc[sl][t][h * 2 + 0] = e0;
                    acc[sl][t][h * 2 + 1] = e1;
                    psum += e0 + e1;
                }
                psum += __shfl_xor_sync(0xffffffffu, psum, 1);
                psum += __shfl_xor_sync(0xffffffffu, psum, 2);
                if (kq == 0) rs_arr[row * 8 + wid] = psum;
            }
        }
        __syncthreads();

        // ---- pass 2: denominators (2x LDS.128), scale, streaming stores ----
        const float4* rsq = reinterpret_cast<const float4*>(rs_arr);
        #pragma unroll
        for (int sl = 0; sl < 2; sl++) {
            #pragma unroll
            for (int h = 0; h < 2; h++) {
                const int row = sl * 16 + h * 8 + g;
                float4 d0 = rsq[row * 2];
                float4 d1 = rsq[row * 2 + 1];
                const float iv = 1.0f / (d0.x + d0.y + d0.z + d0.w +
                                         d1.x + d1.y + d1.z + d1.w);
                float* op = out + ((size_t)tile * BM + row) * KCLS
                                + wid * 64 + kq * 4;
                #pragma unroll
                for (int u = 0; u < 4; u++) {
                    float4 v;
                    v.x = acc[sl][2 * u + 0][h * 2 + 0] * iv;
                    v.y = acc[sl][2 * u + 0][h * 2 + 1] * iv;
                    v.z = acc[sl][2 * u + 1][h * 2 + 0] * iv;
                    v.w = acc[sl][2 * u + 1][h * 2 + 1] * iv;
                    stg_cs(op + u * 16, v);
                }
            }
        }

        // ---- stage next A (after stores, R5 ordering) ----
        if (hn) stage(x, p ^ 1);
        p ^= 1;
        __syncthreads();
    }
}

// ---------------- launch ----------------

extern "C" void kernel_launch(void* const* d_in, const int* in_sizes, int n_in,
                              void* d_out, int out_size) {
    const float* X   = (const float*)d_in[0];   // [N,128]
    const float* muK = (const float*)d_in[1];   // [512,128]
    float* out = (float*)d_out;                 // [N,512]

    static int sms = 0;
    if (!sms) {
        cudaDeviceGetAttribute(&sms, cudaDevAttrMultiProcessorCount, 0);
        if (sms <= 0) sms = 148;
        cudaFuncSetAttribute(ncm_main,
                             cudaFuncAttributeMaxDynamicSharedMemorySize,
                             SM_TOTAL);
    }

    int N = in_sizes[0] / DDIM;
    int tiles = N / BM;                  // 8192
    int nct = sms < tiles ? sms : tiles;

    ncm_prep<<<KCLS, DDIM>>>(muK);
    ncm_main<<<nct, 256, SM_TOTAL>>>(X, out, tiles, nct);
}